// round 6
// baseline (speedup 1.0000x reference)
#include <cuda_runtime.h>
#include <cstdint>

#define DIN  2048
#define BTOT 4096
#define CORE_R_STRIDE 2097152   // 512*512*8
#define CORE_O_STRIDE 4096      // 512*8

// scratch (static device globals; no allocation anywhere)
__device__ float g_Gpart[4 * 8 * 16 * 4096];  // 8 MB
__device__ float g_Gsum [4 * 64 * 512];       // 512 KB
__device__ float g_S    [BTOT * 4 * 64];      // 4 MB   [b][c*64+rs]
__device__ float g_env  [4 * BTOT * 64];      // 4 MB   [c][b][r*8+s]

// ---- f32x2 packed helpers (Blackwell FFMA2) ----
__device__ __forceinline__ unsigned long long pack2(float a, float b) {
    unsigned long long r;
    asm("mov.b64 %0, {%1, %2};" : "=l"(r) : "f"(a), "f"(b));
    return r;
}
__device__ __forceinline__ unsigned long long fma2(unsigned long long a,
                                                   unsigned long long b,
                                                   unsigned long long c) {
    unsigned long long d;
    asm("fma.rn.f32x2 %0, %1, %2, %3;" : "=l"(d) : "l"(a), "l"(b), "l"(c));
    return d;
}
__device__ __forceinline__ void unpack2(unsigned long long v, float& a, float& b) {
    asm("mov.b64 {%0, %1}, %2;" : "=f"(a), "=f"(b) : "l"(v));
}

// ---------------------------------------------------------------------------
// 1a: partial sums over o (32 o per block). bx = c*128 + r*16 + os
__global__ void k_gpart(const float* __restrict__ c0, const float* __restrict__ c1,
                        const float* __restrict__ c2, const float* __restrict__ c3) {
    int bx = blockIdx.x;
    int c = bx >> 7, r = (bx >> 4) & 7, os = bx & 15;
    const float* core = (c == 0) ? c0 : (c == 1) ? c1 : (c == 2) ? c2 : c3;
    const float* base = core + (size_t)r * CORE_R_STRIDE + (size_t)(os * 32) * CORE_O_STRIDE;
    float* dst = g_Gpart + (size_t)bx * 4096;
    for (int k = 0; k < 16; k++) {
        int col = k * 256 + threadIdx.x;
        float s = 0.f;
        #pragma unroll 8
        for (int o = 0; o < 32; o++) s += base[(size_t)o * CORE_O_STRIDE + col];
        dst[col] = s;
    }
}

// 1b: reduce 16 partials -> Gsum[c][r*8+s][x]
__global__ void k_gsum() {
    int idx = blockIdx.x * 256 + threadIdx.x;      // 131072
    int c = idx >> 15, r = (idx >> 12) & 7, col = idx & 4095;
    const float* src = g_Gpart + ((size_t)(c * 8 + r) * 16) * 4096 + col;
    float s = 0.f;
    #pragma unroll
    for (int os = 0; os < 16; os++) s += src[(size_t)os * 4096];
    int x = col >> 3, sd = col & 7;
    g_Gsum[c * 32768 + (r * 8 + sd) * 512 + x] = s;
}

// ---------------------------------------------------------------------------
// 2: S[b][c*64+rs] = sum_x Gsum[c][rs][x] * X[b][c*512+x]
// grid (64 btiles, 4 c); 256 thr = (rs 0..63, bq 0..3); 16 b per thread
__global__ void k_S(const float* __restrict__ X) {
    __shared__ float sxs[64 * 68];   // [x][b]
    __shared__ float sgs[64 * 65];   // [rs][x]
    int btile = blockIdx.x, c = blockIdx.y, tid = threadIdx.x;
    int rs = tid & 63, bq = tid >> 6, b0 = btile * 64;
    float acc[16];
    #pragma unroll
    for (int i = 0; i < 16; i++) acc[i] = 0.f;

    for (int kb = 0; kb < 8; kb++) {
        int xb = kb * 64;
        #pragma unroll
        for (int it = 0; it < 16; it++) {
            int idx = it * 256 + tid;
            int xl = idx & 63, bl = idx >> 6;
            sxs[xl * 68 + bl] = X[(size_t)(b0 + bl) * DIN + c * 512 + xb + xl];
        }
        #pragma unroll
        for (int it = 0; it < 16; it++) {
            int idx = it * 256 + tid;
            int xl = idx & 63, rl = idx >> 6;
            sgs[rl * 65 + xl] = g_Gsum[c * 32768 + rl * 512 + xb + xl];
        }
        __syncthreads();
        #pragma unroll 4
        for (int x = 0; x < 64; x++) {
            float g = sgs[rs * 65 + x];
            const float4* xp = (const float4*)(sxs + x * 68 + bq * 16);
            float4 v0 = xp[0], v1 = xp[1], v2 = xp[2], v3 = xp[3];
            acc[0]  += g * v0.x; acc[1]  += g * v0.y; acc[2]  += g * v0.z; acc[3]  += g * v0.w;
            acc[4]  += g * v1.x; acc[5]  += g * v1.y; acc[6]  += g * v1.z; acc[7]  += g * v1.w;
            acc[8]  += g * v2.x; acc[9]  += g * v2.y; acc[10] += g * v2.z; acc[11] += g * v2.w;
            acc[12] += g * v3.x; acc[13] += g * v3.y; acc[14] += g * v3.z; acc[15] += g * v3.w;
        }
        __syncthreads();
    }
    #pragma unroll
    for (int j = 0; j < 16; j++)
        g_S[(size_t)(b0 + bq * 16 + j) * 256 + c * 64 + rs] = acc[j];
}

// ---------------------------------------------------------------------------
// 3: per-b 8x8 chains. 256 thr = 4 b x 64 lanes (i=t>>3, j=t&7)
// m slots: 0..3 = S0..S3, 4=P2, 5=P3, 6=Q1, 7=Q0
__global__ void k_env() {
    __shared__ float m[4][8][64];
    int tid = threadIdx.x;
    int bl = tid >> 6, t = tid & 63, i = t >> 3, j = t & 7;
    int b = blockIdx.x * 4 + bl;
    const float* sp = g_S + (size_t)b * 256;
    #pragma unroll
    for (int k = 0; k < 4; k++) m[bl][k][t] = sp[k * 64 + t];
    __syncthreads();
    float a = 0.f, q = 0.f;
    #pragma unroll
    for (int k = 0; k < 8; k++) {
        a += m[bl][0][i * 8 + k] * m[bl][1][k * 8 + j];   // P2 = S0*S1
        q += m[bl][2][i * 8 + k] * m[bl][3][k * 8 + j];   // Q1 = S2*S3
    }
    m[bl][4][t] = a; m[bl][6][t] = q;
    __syncthreads();
    float p3 = 0.f, q0 = 0.f;
    #pragma unroll
    for (int k = 0; k < 8; k++) {
        p3 += m[bl][4][i * 8 + k] * m[bl][2][k * 8 + j];  // P3 = P2*S2
        q0 += m[bl][1][i * 8 + k] * m[bl][6][k * 8 + j];  // Q0 = S1*Q1
    }
    m[bl][5][t] = p3; m[bl][7][t] = q0;
    __syncthreads();
    // env_i[r=i, s=j]
    float e1 = 0.f, e2 = 0.f;
    #pragma unroll
    for (int p = 0; p < 8; p++) {
        e1 += m[bl][6][j * 8 + p] * m[bl][0][p * 8 + i];  // Q1[s,p]*S0[p,r]
        e2 += m[bl][3][j * 8 + p] * m[bl][4][p * 8 + i];  // S3[s,p]*P2[p,r]
    }
    size_t bo = (size_t)b * 64 + t;
    g_env[bo]                 = m[bl][7][j * 8 + i];      // env0 = Q0^T
    g_env[(1u << 18) + bo]    = e1;
    g_env[(2u << 18) + bo]    = e2;
    g_env[(3u << 18) + bo]    = m[bl][5][j * 8 + i];      // env3 = P3^T
}

// ---------------------------------------------------------------------------
// 4: main contraction. CTA=(btile of 128, o, c); warp = r; thread = 4 b x 8 s.
#define BT 128
#define KC 128
#define SXP 132
#define SMEM_FLOATS (KC * SXP + 8 * KC * 8 + 8 * BT)   // 26112 -> 104448 B

__global__ void __launch_bounds__(256, 2) k_main(
    const float* __restrict__ X,
    const float* __restrict__ c0, const float* __restrict__ c1,
    const float* __restrict__ c2, const float* __restrict__ c3,
    const float* __restrict__ bias, float* __restrict__ out)
{
    extern __shared__ float smem[];
    float* sx   = smem;                  // [KC][SXP] transposed x chunk
    float* sg   = smem + KC * SXP;       // [8][KC*8] G chunk (r, x, s)
    float* sred = sg + 8 * KC * 8;       // [8][BT]

    int btile = blockIdx.x, o = blockIdx.y, c = blockIdx.z;
    int tid = threadIdx.x, r = tid >> 5, lane = tid & 31;
    int b0 = btile * BT;
    const float* core = (c == 0) ? c0 : (c == 1) ? c1 : (c == 2) ? c2 : c3;
    const float* Xb = X + (size_t)b0 * DIN + c * 512;
    const float* Gob = core + (size_t)r * CORE_R_STRIDE + (size_t)o * CORE_O_STRIDE;

    unsigned long long acc[16];
    #pragma unroll
    for (int i = 0; i < 16; i++) acc[i] = 0ULL;

    for (int kb = 0; kb < 4; kb++) {
        int x0 = kb * KC;
        __syncthreads();
        // x tile: [xl][bl], gmem coalesced, STS 4-way conflict (pitch 132)
        #pragma unroll
        for (int it = 0; it < 64; it++) {
            int idx = it * 256 + tid;
            int xl = idx & 127, bl = idx >> 7;
            sx[xl * SXP + bl] = Xb[(size_t)bl * DIN + x0 + xl];
        }
        // G tile: contiguous 1024 floats per r, float4
        {
            const float4* gsrc = (const float4*)(core + (size_t)o * CORE_O_STRIDE + (size_t)x0 * 8);
            #pragma unroll
            for (int it = 0; it < 8; it++) {
                int idx = it * 256 + tid;
                int rr = idx >> 8, rest = idx & 255;
                ((float4*)(sg + rr * 1024))[rest] =
                    gsrc[(size_t)rr * (CORE_R_STRIDE / 4) + rest];
            }
        }
        __syncthreads();

        const float* sgr = sg + r * 1024;
        #pragma unroll 2
        for (int x = 0; x < KC; x++) {
            ulonglong2 g01 = *(const ulonglong2*)(sgr + x * 8);       // s0s1,s2s3
            ulonglong2 g23 = *(const ulonglong2*)(sgr + x * 8 + 4);   // s4s5,s6s7
            float4 xv = *(const float4*)(sx + x * SXP + lane * 4);
            unsigned long long xb;
            xb = pack2(xv.x, xv.x);
            acc[0]  = fma2(g01.x, xb, acc[0]);  acc[1]  = fma2(g01.y, xb, acc[1]);
            acc[2]  = fma2(g23.x, xb, acc[2]);  acc[3]  = fma2(g23.y, xb, acc[3]);
            xb = pack2(xv.y, xv.y);
            acc[4]  = fma2(g01.x, xb, acc[4]);  acc[5]  = fma2(g01.y, xb, acc[5]);
            acc[6]  = fma2(g23.x, xb, acc[6]);  acc[7]  = fma2(g23.y, xb, acc[7]);
            xb = pack2(xv.z, xv.z);
            acc[8]  = fma2(g01.x, xb, acc[8]);  acc[9]  = fma2(g01.y, xb, acc[9]);
            acc[10] = fma2(g23.x, xb, acc[10]); acc[11] = fma2(g23.y, xb, acc[11]);
            xb = pack2(xv.w, xv.w);
            acc[12] = fma2(g01.x, xb, acc[12]); acc[13] = fma2(g01.y, xb, acc[13]);
            acc[14] = fma2(g23.x, xb, acc[14]); acc[15] = fma2(g23.y, xb, acc[15]);
        }
    }

    // epilogue: contract with env over s, reduce over r
    const float* envc = g_env + ((size_t)c << 18);
    #pragma unroll
    for (int j = 0; j < 4; j++) {
        const float* ev = envc + ((size_t)(b0 + lane * 4 + j)) * 64 + r * 8;
        float4 e0 = *(const float4*)ev;
        float4 e1 = *(const float4*)(ev + 4);
        float a0, a1, s = 0.f;
        unpack2(acc[j * 4 + 0], a0, a1); s += e0.x * a0 + e0.y * a1;
        unpack2(acc[j * 4 + 1], a0, a1); s += e0.z * a0 + e0.w * a1;
        unpack2(acc[j * 4 + 2], a0, a1); s += e1.x * a0 + e1.y * a1;
        unpack2(acc[j * 4 + 3], a0, a1); s += e1.z * a0 + e1.w * a1;
        sred[r * BT + lane * 4 + j] = s;
    }
    __syncthreads();
    if (tid < BT) {
        float s = 0.f;
        #pragma unroll
        for (int rr = 0; rr < 8; rr++) s += sred[rr * BT + tid];
        out[(size_t)(b0 + tid) * 2048 + c * 512 + o] = s + bias[c * 512 + o];
    }
}

// ---------------------------------------------------------------------------
extern "C" void kernel_launch(void* const* d_in, const int* in_sizes, int n_in,
                              void* d_out, int out_size) {
    const float* X  = (const float*)d_in[0];
    const float* c0 = (const float*)d_in[1];
    const float* c1 = (const float*)d_in[2];
    const float* c2 = (const float*)d_in[3];
    const float* c3 = (const float*)d_in[4];
    const float* bias = (const float*)d_in[5];
    float* out = (float*)d_out;

    k_gpart<<<512, 256>>>(c0, c1, c2, c3);
    k_gsum<<<512, 256>>>();
    k_S<<<dim3(64, 4), 256>>>(X);
    k_env<<<1024, 256>>>();

    static int smem_set = 0;
    if (!smem_set) {
        cudaFuncSetAttribute(k_main, cudaFuncAttributeMaxDynamicSharedMemorySize,
                             SMEM_FLOATS * 4);
        smem_set = 1;
    }
    k_main<<<dim3(32, 512, 4), 256, SMEM_FLOATS * 4>>>(X, c0, c1, c2, c3, bias, out);
}

// round 15
// speedup vs baseline: 2.6402x; 2.6402x over previous
#include <cuda_runtime.h>
#include <cuda_bf16.h>
#include <cstdint>

#define DIN  2048
#define BTOT 4096
#define CORE_R_STRIDE 2097152   // 512*512*8
#define CORE_O_STRIDE 4096      // 512*8

// ---------------- scratch (static device globals; no allocation) -----------
__device__ float g_Gpart[4 * 8 * 16 * 4096];        // 8 MB
__device__ float g_Gsum [4 * 64 * 512];             // 512 KB
__device__ float g_S    [BTOT * 4 * 64];            // 4 MB   [b][c*64+rs]
__device__ float g_env  [4 * BTOT * 64];            // 4 MB   [c][b][r*8+s]
__device__ __nv_bfloat16 g_Gph[4ull * 32768 * 512]; // 128 MB [c][n=o*64+r*8+s][x]
__device__ __nv_bfloat16 g_Gpl[4ull * 32768 * 512]; // 128 MB
__device__ __nv_bfloat16 g_Xh [BTOT * DIN];         // 16 MB  [b][x]
__device__ __nv_bfloat16 g_Xl [BTOT * DIN];         // 16 MB

// ---------------- helpers --------------------------------------------------
__device__ __forceinline__ uint32_t smem_u32(const void* p) {
    return (uint32_t)__cvta_generic_to_shared((void*)p);
}
// pack (lo, hi) floats -> bf16x2 (first arg in low 16 bits)
__device__ __forceinline__ uint32_t bf16x2_of(float lo, float hi) {
    uint32_t r;
    asm("cvt.rn.bf16x2.f32 %0, %1, %2;" : "=r"(r) : "f"(hi), "f"(lo));
    return r;
}
__device__ __forceinline__ void cp16(uint32_t dst, const void* src) {
    asm volatile("cp.async.ca.shared.global [%0], [%1], 16;" :: "r"(dst), "l"(src));
}
__device__ __forceinline__ void ldsm4(uint32_t& r0, uint32_t& r1, uint32_t& r2,
                                      uint32_t& r3, uint32_t a) {
    asm volatile("ldmatrix.sync.aligned.m8n8.x4.shared.b16 {%0,%1,%2,%3}, [%4];"
                 : "=r"(r0), "=r"(r1), "=r"(r2), "=r"(r3) : "r"(a));
}
__device__ __forceinline__ void hmma(float* c, uint32_t a0, uint32_t a1,
                                     uint32_t a2, uint32_t a3,
                                     uint32_t b0, uint32_t b1) {
    asm volatile(
        "mma.sync.aligned.m16n8k16.row.col.f32.bf16.bf16.f32 "
        "{%0,%1,%2,%3}, {%4,%5,%6,%7}, {%8,%9}, {%0,%1,%2,%3};"
        : "+f"(c[0]), "+f"(c[1]), "+f"(c[2]), "+f"(c[3])
        : "r"(a0), "r"(a1), "r"(a2), "r"(a3), "r"(b0), "r"(b1));
}

// ---------------------------------------------------------------------------
// 0a: split X -> bf16 hi/lo
__global__ void k_xsplit(const float* __restrict__ X) {
    size_t i4 = (size_t)blockIdx.x * 256 + threadIdx.x;  // < 2097152
    float4 v = ((const float4*)X)[i4];
    uint32_t h01 = bf16x2_of(v.x, v.y);
    uint32_t h23 = bf16x2_of(v.z, v.w);
    uint32_t l01 = bf16x2_of(v.x - __uint_as_float(h01 << 16),
                             v.y - __uint_as_float(h01 & 0xFFFF0000u));
    uint32_t l23 = bf16x2_of(v.z - __uint_as_float(h23 << 16),
                             v.w - __uint_as_float(h23 & 0xFFFF0000u));
    ((uint2*)g_Xh)[i4] = make_uint2(h01, h23);
    ((uint2*)g_Xl)[i4] = make_uint2(l01, l23);
}

// 0b: permute+split G: [r][o][x*8+s] -> Gp[c][n=o*64+r*8+s][x] hi/lo
__global__ void k_gprep(const float* __restrict__ c0, const float* __restrict__ c1,
                        const float* __restrict__ c2, const float* __restrict__ c3) {
    __shared__ float sm[8][513];
    int o = blockIdx.x, r = blockIdx.y, c = blockIdx.z;
    int tid = threadIdx.x;
    const float* core = (c == 0) ? c0 : (c == 1) ? c1 : (c == 2) ? c2 : c3;
    const float4* src = (const float4*)(core + (size_t)r * CORE_R_STRIDE +
                                        (size_t)o * CORE_O_STRIDE);
    #pragma unroll
    for (int j = 0; j < 8; j++) {
        int i4 = j * 128 + tid;
        float4 v = src[i4];
        int x = i4 >> 1, s0 = (i4 & 1) * 4;
        sm[s0 + 0][x] = v.x; sm[s0 + 1][x] = v.y;
        sm[s0 + 2][x] = v.z; sm[s0 + 3][x] = v.w;
    }
    __syncthreads();
    int row = tid >> 4, ch = tid & 15;
    size_t orow = ((size_t)c * 32768 + (size_t)o * 64 + r * 8 + row) * 512;
    #pragma unroll
    for (int g = 0; g < 8; g++) {
        int x0 = ch * 32 + g * 4;
        float a = sm[row][x0], b = sm[row][x0 + 1];
        float e = sm[row][x0 + 2], d = sm[row][x0 + 3];
        uint32_t h01 = bf16x2_of(a, b), h23 = bf16x2_of(e, d);
        uint32_t l01 = bf16x2_of(a - __uint_as_float(h01 << 16),
                                 b - __uint_as_float(h01 & 0xFFFF0000u));
        uint32_t l23 = bf16x2_of(e - __uint_as_float(h23 << 16),
                                 d - __uint_as_float(h23 & 0xFFFF0000u));
        *(uint2*)(g_Gph + orow + x0) = make_uint2(h01, h23);
        *(uint2*)(g_Gpl + orow + x0) = make_uint2(l01, l23);
    }
}

// ---------------------------------------------------------------------------
// 1a/1b: Gsum (fp32 exact) for S
__global__ void k_gpart(const float* __restrict__ c0, const float* __restrict__ c1,
                        const float* __restrict__ c2, const float* __restrict__ c3) {
    int bx = blockIdx.x;
    int c = bx >> 7, r = (bx >> 4) & 7, os = bx & 15;
    const float* core = (c == 0) ? c0 : (c == 1) ? c1 : (c == 2) ? c2 : c3;
    const float* base = core + (size_t)r * CORE_R_STRIDE + (size_t)(os * 32) * CORE_O_STRIDE;
    float* dst = g_Gpart + (size_t)bx * 4096;
    for (int k = 0; k < 16; k++) {
        int col = k * 256 + threadIdx.x;
        float s = 0.f;
        #pragma unroll 8
        for (int o = 0; o < 32; o++) s += base[(size_t)o * CORE_O_STRIDE + col];
        dst[col] = s;
    }
}
__global__ void k_gsum() {
    int idx = blockIdx.x * 256 + threadIdx.x;
    int c = idx >> 15, r = (idx >> 12) & 7, col = idx & 4095;
    const float* src = g_Gpart + ((size_t)(c * 8 + r) * 16) * 4096 + col;
    float s = 0.f;
    #pragma unroll
    for (int os = 0; os < 16; os++) s += src[(size_t)os * 4096];
    int x = col >> 3, sd = col & 7;
    g_Gsum[c * 32768 + (r * 8 + sd) * 512 + x] = s;
}

// 2: S (fp32 exact)
__global__ void k_S(const float* __restrict__ X) {
    __shared__ float sxs[64 * 68];
    __shared__ float sgs[64 * 65];
    int btile = blockIdx.x, c = blockIdx.y, tid = threadIdx.x;
    int rs = tid & 63, bq = tid >> 6, b0 = btile * 64;
    float acc[16];
    #pragma unroll
    for (int i = 0; i < 16; i++) acc[i] = 0.f;
    for (int kb = 0; kb < 8; kb++) {
        int xb = kb * 64;
        #pragma unroll
        for (int it = 0; it < 16; it++) {
            int idx = it * 256 + tid;
            int xl = idx & 63, bl = idx >> 6;
            sxs[xl * 68 + bl] = X[(size_t)(b0 + bl) * DIN + c * 512 + xb + xl];
        }
        #pragma unroll
        for (int it = 0; it < 16; it++) {
            int idx = it * 256 + tid;
            int xl = idx & 63, rl = idx >> 6;
            sgs[rl * 65 + xl] = g_Gsum[c * 32768 + rl * 512 + xb + xl];
        }
        __syncthreads();
        #pragma unroll 4
        for (int x = 0; x < 64; x++) {
            float g = sgs[rs * 65 + x];
            const float4* xp = (const float4*)(sxs + x * 68 + bq * 16);
            float4 v0 = xp[0], v1 = xp[1], v2 = xp[2], v3 = xp[3];
            acc[0]  += g * v0.x; acc[1]  += g * v0.y; acc[2]  += g * v0.z; acc[3]  += g * v0.w;
            acc[4]  += g * v1.x; acc[5]  += g * v1.y; acc[6]  += g * v1.z; acc[7]  += g * v1.w;
            acc[8]  += g * v2.x; acc[9]  += g * v2.y; acc[10] += g * v2.z; acc[11] += g * v2.w;
            acc[12] += g * v3.x; acc[13] += g * v3.y; acc[14] += g * v3.z; acc[15] += g * v3.w;
        }
        __syncthreads();
    }
    #pragma unroll
    for (int j = 0; j < 16; j++)
        g_S[(size_t)(b0 + bq * 16 + j) * 256 + c * 64 + rs] = acc[j];
}

// 3: per-b 8x8 chains -> env
__global__ void k_env() {
    __shared__ float m[4][8][64];
    int tid = threadIdx.x;
    int bl = tid >> 6, t = tid & 63, i = t >> 3, j = t & 7;
    int b = blockIdx.x * 4 + bl;
    const float* sp = g_S + (size_t)b * 256;
    #pragma unroll
    for (int k = 0; k < 4; k++) m[bl][k][t] = sp[k * 64 + t];
    __syncthreads();
    float a = 0.f, q = 0.f;
    #pragma unroll
    for (int k = 0; k < 8; k++) {
        a += m[bl][0][i * 8 + k] * m[bl][1][k * 8 + j];
        q += m[bl][2][i * 8 + k] * m[bl][3][k * 8 + j];
    }
    m[bl][4][t] = a; m[bl][6][t] = q;
    __syncthreads();
    float p3 = 0.f, q0 = 0.f;
    #pragma unroll
    for (int k = 0; k < 8; k++) {
        p3 += m[bl][4][i * 8 + k] * m[bl][2][k * 8 + j];
        q0 += m[bl][1][i * 8 + k] * m[bl][6][k * 8 + j];
    }
    m[bl][5][t] = p3; m[bl][7][t] = q0;
    __syncthreads();
    float e1 = 0.f, e2 = 0.f;
    #pragma unroll
    for (int p = 0; p < 8; p++) {
        e1 += m[bl][6][j * 8 + p] * m[bl][0][p * 8 + i];
        e2 += m[bl][3][j * 8 + p] * m[bl][4][p * 8 + i];
    }
    size_t bo = (size_t)b * 64 + t;
    g_env[bo]              = m[bl][7][j * 8 + i];
    g_env[(1u << 18) + bo] = e1;
    g_env[(2u << 18) + bo] = e2;
    g_env[(3u << 18) + bo] = m[bl][5][j * 8 + i];
}

// ---------------------------------------------------------------------------
// 4: mma.sync GEMM + exact fp32 env epilogue.
// CTA: 128 b x 128 n (n = o*64 + rs), K=512 (x), 3-term bf16 split.
#define TILE_B  10240            // 128 rows * 80 B pitch
#define STAGE_B (4 * TILE_B)     // Ah, Al, Bh, Bl
#define SMEM_MAIN (3 * STAGE_B)  // 122880

__global__ void __launch_bounds__(256, 1) k_main(
    const float* __restrict__ bias, float* __restrict__ out)
{
    extern __shared__ __align__(128) char smem[];
    uint32_t sb = smem_u32(smem);
    int tid = threadIdx.x, wid = tid >> 5, lane = tid & 31;
    int btile = blockIdx.x, nt = blockIdx.y, c = blockIdx.z;
    int b0 = btile * 128;
    size_t n0 = (size_t)nt * 128;
    int wm = wid >> 2, wn = wid & 3;

    float acc[64];
    #pragma unroll
    for (int i = 0; i < 64; i++) acc[i] = 0.f;

    // cp.async geometry: thread -> (row rr / rr+64, 16B quad q)
    int q = tid & 3, rr = tid >> 2;
    const __nv_bfloat16* xh0 = g_Xh + (size_t)(b0 + rr) * DIN + c * 512 + q * 8;
    const __nv_bfloat16* xl0 = g_Xl + (size_t)(b0 + rr) * DIN + c * 512 + q * 8;
    const __nv_bfloat16* gh0 = g_Gph + ((size_t)c * 32768 + n0 + rr) * 512 + q * 8;
    const __nv_bfloat16* gl0 = g_Gpl + ((size_t)c * 32768 + n0 + rr) * 512 + q * 8;
    uint32_t d0 = sb + rr * 80 + q * 16;
    uint32_t d1 = sb + (rr + 64) * 80 + q * 16;

    #define LOAD_STAGE(st, kx) do {                                        \
        uint32_t bb = (uint32_t)((st) * STAGE_B);                          \
        int ko = (kx) * 32;                                                \
        cp16(d0 + bb,              xh0 + ko);                              \
        cp16(d1 + bb,              xh0 + (size_t)64 * DIN + ko);           \
        cp16(d0 + bb + TILE_B,     xl0 + ko);                              \
        cp16(d1 + bb + TILE_B,     xl0 + (size_t)64 * DIN + ko);           \
        cp16(d0 + bb + 2 * TILE_B, gh0 + ko);                              \
        cp16(d1 + bb + 2 * TILE_B, gh0 + (size_t)64 * 512 + ko);           \
        cp16(d0 + bb + 3 * TILE_B, gl0 + ko);                              \
        cp16(d1 + bb + 3 * TILE_B, gl0 + (size_t)64 * 512 + ko);           \
    } while (0)

    uint32_t aoff = sb + (uint32_t)((wm * 64 + (lane & 15)) * 80 + (lane >> 4) * 16);
    uint32_t boff = sb + 2 * TILE_B +
        (uint32_t)((wn * 32 + (lane >> 4) * 8 + (lane & 7)) * 80 +
                   ((lane >> 3) & 1) * 16);

    LOAD_STAGE(0, 0);
    asm volatile("cp.async.commit_group;" ::: "memory");
    LOAD_STAGE(1, 1);
    asm volatile("cp.async.commit_group;" ::: "memory");

    #pragma unroll 1
    for (int kx = 0; kx < 16; kx++) {
        asm volatile("cp.async.wait_group 1;" ::: "memory");
        __syncthreads();
        if (kx + 2 < 16) LOAD_STAGE((kx + 2) % 3, kx + 2);
        asm volatile("cp.async.commit_group;" ::: "memory");

        uint32_t bb = (uint32_t)((kx % 3) * STAGE_B);
        #pragma unroll
        for (int k16 = 0; k16 < 2; k16++) {
            uint32_t ah[16], al[16], bh[8], bl2[8];
            #pragma unroll
            for (int t = 0; t < 4; t++) {
                ldsm4(ah[t*4], ah[t*4+1], ah[t*4+2], ah[t*4+3],
                      bb + aoff + t * 1280 + k16 * 32);
                ldsm4(al[t*4], al[t*4+1], al[t*4+2], al[t*4+3],
                      bb + aoff + TILE_B + t * 1280 + k16 * 32);
            }
            #pragma unroll
            for (int p = 0; p < 2; p++) {
                ldsm4(bh[p*4], bh[p*4+1], bh[p*4+2], bh[p*4+3],
                      bb + boff + p * 1280 + k16 * 32);
                ldsm4(bl2[p*4], bl2[p*4+1], bl2[p*4+2], bl2[p*4+3],
                      bb + boff + TILE_B + p * 1280 + k16 * 32);
            }
            #pragma unroll
            for (int t = 0; t < 4; t++)
                #pragma unroll
                for (int n = 0; n < 4; n++) {
                    float* cc = &acc[(t * 4 + n) * 4];
                    int bi = (n >> 1) * 4 + (n & 1) * 2;
                    hmma(cc, ah[t*4], ah[t*4+1], ah[t*4+2], ah[t*4+3],
                         bh[bi], bh[bi + 1]);
                    hmma(cc, ah[t*4], ah[t*4+1], ah[t*4+2], ah[t*4+3],
                         bl2[bi], bl2[bi + 1]);
                    hmma(cc, al[t*4], al[t*4+1], al[t*4+2], al[t*4+3],
                         bh[bi], bh[bi + 1]);
                }
        }
    }
    asm volatile("cp.async.wait_group 0;" ::: "memory");
    __syncthreads();

    // ---- epilogue: out[b,o] = sum_rs env[b,rs] * acc  (exact fp32) ----
    float* es = (float*)smem;                  // [128][68] padded
    float* pw = (float*)(smem + 34816);        // [8][64]
    {
        const float4* envsrc = (const float4*)(g_env + ((size_t)c << 18) +
                                               (size_t)b0 * 64);
        #pragma unroll
        for (int j = 0; j < 8; j++) {
            int idx = j * 256 + tid;           // 2048 float4
            int blr = idx >> 4, part = idx & 15;
            ((float4*)(es + blr * 68))[part] = envsrc[idx];
        }
    }
    __syncthreads();
    #pragma unroll
    for (int t = 0; t < 4; t++)
        #pragma unroll
        for (int h = 0; h < 2; h++) {
            int blr = wm * 64 + t * 16 + h * 8 + (lane >> 2);
            float p = 0.f;
            #pragma unroll
            for (int n = 0; n < 4; n++) {
                int nc = wn * 32 + n * 8 + (lane & 3) * 2;
                p += es[blr * 68 + (nc & 63)]       * acc[(t*4+n)*4 + h*2];
                p += es[blr * 68 + ((nc + 1) & 63)] * acc[(t*4+n)*4 + h*2 + 1];
            }
            p += __shfl_xor_sync(0xffffffff, p, 1);
            p += __shfl_xor_sync(0xffffffff, p, 2);
            if ((lane & 3) == 0)
                pw[wid * 64 + t * 16 + h * 8 + (lane >> 2)] = p;
        }
    __syncthreads();
    {
        int blr = tid >> 1, os = tid & 1;
        int wb = (blr >> 6) * 4 + os * 2;
        float v = pw[wb * 64 + (blr & 63)] + pw[(wb + 1) * 64 + (blr & 63)];
        int og = nt * 2 + os;
        out[(size_t)(b0 + blr) * 2048 + c * 512 + og] = v + bias[c * 512 + og];
    }
}

// ---------------------------------------------------------------------------
extern "C" void kernel_launch(void* const* d_in, const int* in_sizes, int n_in,
                              void* d_out, int out_size) {
    const float* X  = (const float*)d_in[0];
    const float* c0 = (const float*)d_in[1];
    const float* c1 = (const float*)d_in[2];
    const float* c2 = (const float*)d_in[3];
    const float* c3 = (const float*)d_in[4];
    const float* bias = (const float*)d_in[5];
    float* out = (float*)d_out;

    k_xsplit<<<8192, 256>>>(X);
    k_gprep<<<dim3(512, 8, 4), 128>>>(c0, c1, c2, c3);
    k_gpart<<<512, 256>>>(c0, c1, c2, c3);
    k_gsum<<<512, 256>>>();
    k_S<<<dim3(64, 4), 256>>>(X);
    k_env<<<1024, 256>>>();

    static int attr_set = 0;
    if (!attr_set) {
        cudaFuncSetAttribute(k_main, cudaFuncAttributeMaxDynamicSharedMemorySize,
                             SMEM_MAIN);
        attr_set = 1;
    }
    k_main<<<dim3(32, 256, 4), 256, SMEM_MAIN>>>(bias, out);
}

// round 16
// speedup vs baseline: 2.9451x; 1.1155x over previous
#include <cuda_runtime.h>
#include <cuda_bf16.h>
#include <cstdint>

#define DIN  2048
#define BTOT 4096
#define CORE_R_STRIDE 2097152   // 512*512*8
#define CORE_O_STRIDE 4096      // 512*8

// ---------------- scratch (static device globals; no allocation) -----------
__device__ float g_Gsum [4 * 64 * 512];             // 512 KB
__device__ float g_S    [BTOT * 4 * 64];            // 4 MB   [b][c*64+rs]
__device__ float g_env  [4 * BTOT * 64];            // 4 MB   [c][b][r*8+s]
__device__ __nv_bfloat16 g_Gph[4ull * 32768 * 512]; // 128 MB [c][n=o*64+r*8+s][x]
__device__ __nv_bfloat16 g_Gpl[4ull * 32768 * 512]; // 128 MB
__device__ __nv_bfloat16 g_Xh [BTOT * DIN];         // 16 MB  [b][x]
__device__ __nv_bfloat16 g_Xl [BTOT * DIN];         // 16 MB

// ---------------- helpers --------------------------------------------------
__device__ __forceinline__ uint32_t smem_u32(const void* p) {
    return (uint32_t)__cvta_generic_to_shared((void*)p);
}
__device__ __forceinline__ uint32_t bf16x2_of(float lo, float hi) {
    uint32_t r;
    asm("cvt.rn.bf16x2.f32 %0, %1, %2;" : "=r"(r) : "f"(hi), "f"(lo));
    return r;
}
__device__ __forceinline__ void cp16(uint32_t dst, const void* src) {
    asm volatile("cp.async.ca.shared.global [%0], [%1], 16;" :: "r"(dst), "l"(src));
}
__device__ __forceinline__ void ldsm4(uint32_t& r0, uint32_t& r1, uint32_t& r2,
                                      uint32_t& r3, uint32_t a) {
    asm volatile("ldmatrix.sync.aligned.m8n8.x4.shared.b16 {%0,%1,%2,%3}, [%4];"
                 : "=r"(r0), "=r"(r1), "=r"(r2), "=r"(r3) : "r"(a));
}
__device__ __forceinline__ void hmma(float* c, uint32_t a0, uint32_t a1,
                                     uint32_t a2, uint32_t a3,
                                     uint32_t b0, uint32_t b1) {
    asm volatile(
        "mma.sync.aligned.m16n8k16.row.col.f32.bf16.bf16.f32 "
        "{%0,%1,%2,%3}, {%4,%5,%6,%7}, {%8,%9}, {%0,%1,%2,%3};"
        : "+f"(c[0]), "+f"(c[1]), "+f"(c[2]), "+f"(c[3])
        : "r"(a0), "r"(a1), "r"(a2), "r"(a3), "r"(b0), "r"(b1));
}

// ---------------------------------------------------------------------------
// k_prep: fused (a) X split, (b) G permute+split, (c) direct Gsum.
//   blocks [0, 8192)        : X -> Xh/Xl
//   blocks [8192, 24576)    : G[r][o][x*8+s] -> Gp[c][o*64+r*8+s][x] hi/lo
//   blocks [24576, 25088)   : Gsum[c][r*8+s][x] = sum_o G
__global__ void k_prep(const float* __restrict__ X,
                       const float* __restrict__ c0, const float* __restrict__ c1,
                       const float* __restrict__ c2, const float* __restrict__ c3) {
    __shared__ float sm[8][513];
    int bid = blockIdx.x, tid = threadIdx.x;

    if (bid < 8192) {                       // ---- X split ----
        size_t i4 = (size_t)bid * 256 + tid;
        float4 v = ((const float4*)X)[i4];
        uint32_t h01 = bf16x2_of(v.x, v.y);
        uint32_t h23 = bf16x2_of(v.z, v.w);
        uint32_t l01 = bf16x2_of(v.x - __uint_as_float(h01 << 16),
                                 v.y - __uint_as_float(h01 & 0xFFFF0000u));
        uint32_t l23 = bf16x2_of(v.z - __uint_as_float(h23 << 16),
                                 v.w - __uint_as_float(h23 & 0xFFFF0000u));
        ((uint2*)g_Xh)[i4] = make_uint2(h01, h23);
        ((uint2*)g_Xl)[i4] = make_uint2(l01, l23);
        return;
    }
    if (bid < 24576) {                      // ---- G permute + split ----
        int id = bid - 8192;
        int o = id & 511, r = (id >> 9) & 7, c = id >> 12;
        const float* core = (c == 0) ? c0 : (c == 1) ? c1 : (c == 2) ? c2 : c3;
        const float4* src = (const float4*)(core + (size_t)r * CORE_R_STRIDE +
                                            (size_t)o * CORE_O_STRIDE);
        #pragma unroll
        for (int j = 0; j < 4; j++) {
            int i4 = j * 256 + tid;
            float4 v = src[i4];
            int x = i4 >> 1, s0 = (i4 & 1) * 4;
            sm[s0 + 0][x] = v.x; sm[s0 + 1][x] = v.y;
            sm[s0 + 2][x] = v.z; sm[s0 + 3][x] = v.w;
        }
        __syncthreads();
        int row = tid >> 5, ch = tid & 31;
        size_t orow = ((size_t)c * 32768 + (size_t)o * 64 + r * 8 + row) * 512;
        #pragma unroll
        for (int g = 0; g < 4; g++) {
            int x0 = ch * 16 + g * 4;
            float a = sm[row][x0], b = sm[row][x0 + 1];
            float e = sm[row][x0 + 2], d = sm[row][x0 + 3];
            uint32_t h01 = bf16x2_of(a, b), h23 = bf16x2_of(e, d);
            uint32_t l01 = bf16x2_of(a - __uint_as_float(h01 << 16),
                                     b - __uint_as_float(h01 & 0xFFFF0000u));
            uint32_t l23 = bf16x2_of(e - __uint_as_float(h23 << 16),
                                     d - __uint_as_float(h23 & 0xFFFF0000u));
            *(uint2*)(g_Gph + orow + x0) = make_uint2(h01, h23);
            *(uint2*)(g_Gpl + orow + x0) = make_uint2(l01, l23);
        }
        return;
    }
    {                                       // ---- direct Gsum ----
        int id = bid - 24576;               // 512 blocks
        int c = id >> 7, r = (id >> 4) & 7, co = id & 15;
        const float* core = (c == 0) ? c0 : (c == 1) ? c1 : (c == 2) ? c2 : c3;
        const float* base = core + (size_t)r * CORE_R_STRIDE;
        int col = co * 256 + tid;
        float s = 0.f;
        #pragma unroll 8
        for (int o = 0; o < 512; o++) s += base[(size_t)o * CORE_O_STRIDE + col];
        int x = col >> 3, sd = col & 7;
        g_Gsum[c * 32768 + (r * 8 + sd) * 512 + x] = s;
    }
}

// ---------------------------------------------------------------------------
// k_S: S[b][c*64+rs] = sum_x Gsum[c][rs][x] * X[b][c*512+x]  (fp32 exact)
__global__ void k_S(const float* __restrict__ X) {
    __shared__ float sxs[64 * 68];
    __shared__ float sgs[64 * 65];
    int btile = blockIdx.x, c = blockIdx.y, tid = threadIdx.x;
    int rs = tid & 63, bq = tid >> 6, b0 = btile * 64;
    float acc[16];
    #pragma unroll
    for (int i = 0; i < 16; i++) acc[i] = 0.f;
    for (int kb = 0; kb < 8; kb++) {
        int xb = kb * 64;
        #pragma unroll
        for (int it = 0; it < 16; it++) {
            int idx = it * 256 + tid;
            int xl = idx & 63, bl = idx >> 6;
            sxs[xl * 68 + bl] = X[(size_t)(b0 + bl) * DIN + c * 512 + xb + xl];
        }
        #pragma unroll
        for (int it = 0; it < 16; it++) {
            int idx = it * 256 + tid;
            int xl = idx & 63, rl = idx >> 6;
            sgs[rl * 65 + xl] = g_Gsum[c * 32768 + rl * 512 + xb + xl];
        }
        __syncthreads();
        #pragma unroll 4
        for (int x = 0; x < 64; x++) {
            float g = sgs[rs * 65 + x];
            const float4* xp = (const float4*)(sxs + x * 68 + bq * 16);
            float4 v0 = xp[0], v1 = xp[1], v2 = xp[2], v3 = xp[3];
            acc[0]  += g * v0.x; acc[1]  += g * v0.y; acc[2]  += g * v0.z; acc[3]  += g * v0.w;
            acc[4]  += g * v1.x; acc[5]  += g * v1.y; acc[6]  += g * v1.z; acc[7]  += g * v1.w;
            acc[8]  += g * v2.x; acc[9]  += g * v2.y; acc[10] += g * v2.z; acc[11] += g * v2.w;
            acc[12] += g * v3.x; acc[13] += g * v3.y; acc[14] += g * v3.z; acc[15] += g * v3.w;
        }
        __syncthreads();
    }
    #pragma unroll
    for (int j = 0; j < 16; j++)
        g_S[(size_t)(b0 + bq * 16 + j) * 256 + c * 64 + rs] = acc[j];
}

// ---------------------------------------------------------------------------
// k_env: per-b 8x8 chains -> env
__global__ void k_env() {
    __shared__ float m[4][8][64];
    int tid = threadIdx.x;
    int bl = tid >> 6, t = tid & 63, i = t >> 3, j = t & 7;
    int b = blockIdx.x * 4 + bl;
    const float* sp = g_S + (size_t)b * 256;
    #pragma unroll
    for (int k = 0; k < 4; k++) m[bl][k][t] = sp[k * 64 + t];
    __syncthreads();
    float a = 0.f, q = 0.f;
    #pragma unroll
    for (int k = 0; k < 8; k++) {
        a += m[bl][0][i * 8 + k] * m[bl][1][k * 8 + j];
        q += m[bl][2][i * 8 + k] * m[bl][3][k * 8 + j];
    }
    m[bl][4][t] = a; m[bl][6][t] = q;
    __syncthreads();
    float p3 = 0.f, q0 = 0.f;
    #pragma unroll
    for (int k = 0; k < 8; k++) {
        p3 += m[bl][4][i * 8 + k] * m[bl][2][k * 8 + j];
        q0 += m[bl][1][i * 8 + k] * m[bl][6][k * 8 + j];
    }
    m[bl][5][t] = p3; m[bl][7][t] = q0;
    __syncthreads();
    float e1 = 0.f, e2 = 0.f;
    #pragma unroll
    for (int p = 0; p < 8; p++) {
        e1 += m[bl][6][j * 8 + p] * m[bl][0][p * 8 + i];
        e2 += m[bl][3][j * 8 + p] * m[bl][4][p * 8 + i];
    }
    size_t bo = (size_t)b * 64 + t;
    g_env[bo]              = m[bl][7][j * 8 + i];
    g_env[(1u << 18) + bo] = e1;
    g_env[(2u << 18) + bo] = e2;
    g_env[(3u << 18) + bo] = m[bl][5][j * 8 + i];
}

// ---------------------------------------------------------------------------
// k_main: mma.sync GEMM + exact fp32 env epilogue.
// CTA: 128 b x 128 n, K=512, 3-term bf16 split, 2-stage double buffer,
// 2 CTAs/SM.
#define TILE_B  10240            // 128 rows * 80 B pitch
#define STAGE_B (4 * TILE_B)     // Ah, Al, Bh, Bl
#define SMEM_MAIN (2 * STAGE_B)  // 81920

__global__ void __launch_bounds__(256, 2) k_main(
    const float* __restrict__ bias, float* __restrict__ out)
{
    extern __shared__ __align__(128) char smem[];
    uint32_t sb = smem_u32(smem);
    int tid = threadIdx.x, wid = tid >> 5, lane = tid & 31;
    int btile = blockIdx.x, nt = blockIdx.y, c = blockIdx.z;
    int b0 = btile * 128;
    size_t n0 = (size_t)nt * 128;
    int wm = wid >> 2, wn = wid & 3;

    float acc[64];
    #pragma unroll
    for (int i = 0; i < 64; i++) acc[i] = 0.f;

    int q = tid & 3, rr = tid >> 2;
    const __nv_bfloat16* xh0 = g_Xh + (size_t)(b0 + rr) * DIN + c * 512 + q * 8;
    const __nv_bfloat16* xl0 = g_Xl + (size_t)(b0 + rr) * DIN + c * 512 + q * 8;
    const __nv_bfloat16* gh0 = g_Gph + ((size_t)c * 32768 + n0 + rr) * 512 + q * 8;
    const __nv_bfloat16* gl0 = g_Gpl + ((size_t)c * 32768 + n0 + rr) * 512 + q * 8;
    uint32_t d0 = sb + rr * 80 + q * 16;
    uint32_t d1 = sb + (rr + 64) * 80 + q * 16;

    #define LOAD_STAGE(st, kx) do {                                        \
        uint32_t bb = (uint32_t)((st) * STAGE_B);                          \
        int ko = (kx) * 32;                                                \
        cp16(d0 + bb,              xh0 + ko);                              \
        cp16(d1 + bb,              xh0 + (size_t)64 * DIN + ko);           \
        cp16(d0 + bb + TILE_B,     xl0 + ko);                              \
        cp16(d1 + bb + TILE_B,     xl0 + (size_t)64 * DIN + ko);           \
        cp16(d0 + bb + 2 * TILE_B, gh0 + ko);                              \
        cp16(d1 + bb + 2 * TILE_B, gh0 + (size_t)64 * 512 + ko);           \
        cp16(d0 + bb + 3 * TILE_B, gl0 + ko);                              \
        cp16(d1 + bb + 3 * TILE_B, gl0 + (size_t)64 * 512 + ko);           \
    } while (0)

    uint32_t aoff = sb + (uint32_t)((wm * 64 + (lane & 15)) * 80 + (lane >> 4) * 16);
    uint32_t boff = sb + 2 * TILE_B +
        (uint32_t)((wn * 32 + (lane >> 4) * 8 + (lane & 7)) * 80 +
                   ((lane >> 3) & 1) * 16);

    LOAD_STAGE(0, 0);
    asm volatile("cp.async.commit_group;" ::: "memory");
    LOAD_STAGE(1, 1);
    asm volatile("cp.async.commit_group;" ::: "memory");

    #pragma unroll 1
    for (int kx = 0; kx < 16; kx++) {
        asm volatile("cp.async.wait_group 1;" ::: "memory");
        __syncthreads();

        uint32_t bb = (uint32_t)((kx & 1) * STAGE_B);
        #pragma unroll
        for (int k16 = 0; k16 < 2; k16++) {
            // wave 1: hi * hi
            uint32_t ah[16], bh[8];
            #pragma unroll
            for (int t = 0; t < 4; t++)
                ldsm4(ah[t*4], ah[t*4+1], ah[t*4+2], ah[t*4+3],
                      bb + aoff + t * 1280 + k16 * 32);
            #pragma unroll
            for (int p = 0; p < 2; p++)
                ldsm4(bh[p*4], bh[p*4+1], bh[p*4+2], bh[p*4+3],
                      bb + boff + p * 1280 + k16 * 32);
            #pragma unroll
            for (int t = 0; t < 4; t++)
                #pragma unroll
                for (int n = 0; n < 4; n++) {
                    int bi = (n >> 1) * 4 + (n & 1) * 2;
                    hmma(&acc[(t * 4 + n) * 4], ah[t*4], ah[t*4+1], ah[t*4+2],
                         ah[t*4+3], bh[bi], bh[bi + 1]);
                }
            // wave 2: hi * lo
            {
                uint32_t bl2[8];
                #pragma unroll
                for (int p = 0; p < 2; p++)
                    ldsm4(bl2[p*4], bl2[p*4+1], bl2[p*4+2], bl2[p*4+3],
                          bb + boff + TILE_B + p * 1280 + k16 * 32);
                #pragma unroll
                for (int t = 0; t < 4; t++)
                    #pragma unroll
                    for (int n = 0; n < 4; n++) {
                        int bi = (n >> 1) * 4 + (n & 1) * 2;
                        hmma(&acc[(t * 4 + n) * 4], ah[t*4], ah[t*4+1],
                             ah[t*4+2], ah[t*4+3], bl2[bi], bl2[bi + 1]);
                    }
            }
            // wave 3: lo * hi
            {
                uint32_t al[16];
                #pragma unroll
                for (int t = 0; t < 4; t++)
                    ldsm4(al[t*4], al[t*4+1], al[t*4+2], al[t*4+3],
                          bb + aoff + TILE_B + t * 1280 + k16 * 32);
                #pragma unroll
                for (int t = 0; t < 4; t++)
                    #pragma unroll
                    for (int n = 0; n < 4; n++) {
                        int bi = (n >> 1) * 4 + (n & 1) * 2;
                        hmma(&acc[(t * 4 + n) * 4], al[t*4], al[t*4+1],
                             al[t*4+2], al[t*4+3], bh[bi], bh[bi + 1]);
                    }
            }
        }

        __syncthreads();
        if (kx + 2 < 16) LOAD_STAGE(kx & 1, kx + 2);
        asm volatile("cp.async.commit_group;" ::: "memory");
    }
    asm volatile("cp.async.wait_group 0;" ::: "memory");
    __syncthreads();

    // ---- epilogue: out[b,o] = sum_rs env[b,rs] * acc  (exact fp32) ----
    float* es = (float*)smem;                  // [128][68] padded
    float* pw = (float*)(smem + 34816);        // [8][64]
    {
        const float4* envsrc = (const float4*)(g_env + ((size_t)c << 18) +
                                               (size_t)b0 * 64);
        #pragma unroll
        for (int j = 0; j < 8; j++) {
            int idx = j * 256 + tid;
            int blr = idx >> 4, part = idx & 15;
            ((float4*)(es + blr * 68))[part] = envsrc[idx];
        }
    }
    __syncthreads();
    #pragma unroll
    for (int t = 0; t < 4; t++)
        #pragma unroll
        for (int h = 0; h < 2; h++) {
            int blr = wm * 64 + t * 16 + h * 8 + (lane >> 2);
            float p = 0.f;
            #pragma unroll
            for (int n = 0; n < 4; n++) {
                int nc = wn * 32 + n * 8 + (lane & 3) * 2;
                p += es[blr * 68 + (nc & 63)]       * acc[(t*4+n)*4 + h*2];
                p += es[blr * 68 + ((nc + 1) & 63)] * acc[(t*4+n)*4 + h*2 + 1];
            }
            p += __shfl_xor_sync(0xffffffff, p, 1);
            p += __shfl_xor_sync(0xffffffff, p, 2);
            if ((lane & 3) == 0)
                pw[wid * 64 + t * 16 + h * 8 + (lane >> 2)] = p;
        }
    __syncthreads();
    {
        int blr = tid >> 1, os = tid & 1;
        int wb = (blr >> 6) * 4 + os * 2;
        float v = pw[wb * 64 + (blr & 63)] + pw[(wb + 1) * 64 + (blr & 63)];
        int og = nt * 2 + os;
        out[(size_t)(b0 + blr) * 2048 + c * 512 + og] = v + bias[c * 512 + og];
    }
}

// ---------------------------------------------------------------------------
extern "C" void kernel_launch(void* const* d_in, const int* in_sizes, int n_in,
                              void* d_out, int out_size) {
    const float* X  = (const float*)d_in[0];
    const float* c0 = (const float*)d_in[1];
    const float* c1 = (const float*)d_in[2];
    const float* c2 = (const float*)d_in[3];
    const float* c3 = (const float*)d_in[4];
    const float* bias = (const float*)d_in[5];
    float* out = (float*)d_out;

    k_prep<<<25088, 256>>>(X, c0, c1, c2, c3);
    k_S<<<dim3(64, 4), 256>>>(X);
    k_env<<<1024, 256>>>();

    static int attr_set = 0;
    if (!attr_set) {
        cudaFuncSetAttribute(k_main, cudaFuncAttributeMaxDynamicSharedMemorySize,
                             SMEM_MAIN);
        attr_set = 1;
    }
    k_main<<<dim3(32, 256, 4), 256, SMEM_MAIN>>>(bias, out);
}